// round 16
// baseline (speedup 1.0000x reference)
#include <cuda_runtime.h>
#include <cuda_bf16.h>
#include <cstdint>
#include <math.h>

#define HID   128
#define NMAX  100000
#define EMAX  1600000
#define TE    128    // edges per tile in edge kernel
#define LDW   136    // bf16 row stride in node_post smem
#define SROW  144    // fp8 row stride in edge-kernel smem (36-bank offset)

typedef unsigned long long ull;
typedef unsigned int u32;
typedef unsigned short u16;

// Scratch (static device globals — no runtime allocation).
// g_cnt / g_done rely on static zero-init; both are restored to 0 by k_scan12
// each run, so every graph replay sees the same initial state (deterministic).
__device__ __nv_bfloat16 g_Abf[(size_t)NMAX * HID];  // per-node dst term (bf16)
__device__ __nv_bfloat16 g_Bbf[(size_t)NMAX * HID];  // per-node src term (bf16)
__device__ u32 g_w2f8[HID * (SROW/4)];               // w2^T e4m3 [c][144B rows]
__device__ __nv_bfloat16 g_w3bf[HID * HID];          // [k][c] linear bf16
__device__ __nv_bfloat16 g_w4bf[HID * HID];
__device__ int   g_AGG[(size_t)NMAX * HID]; // relu(segment_max) as float bits
__device__ int   g_cnt[NMAX];               // per-dst degree (zero at kernel entry)
__device__ int   g_off[NMAX];               // block-local exclusive offsets (cursors)
__device__ int   g_bsum[128];               // per-scan-block totals (scanned)
__device__ int   g_done;                    // scan completion counter (self-reset)
__device__ int2  g_sedge[EMAX];             // (src, dst) sorted by dst

// ---- helpers ---------------------------------------------------------------
__device__ __forceinline__ u32 smaddr(const void* p) {
    return (u32)__cvta_generic_to_shared(p);
}
__device__ __forceinline__ void ldsm_x4(u32* r, u32 a) {
    asm volatile("ldmatrix.sync.aligned.m8n8.x4.shared.b16 {%0,%1,%2,%3}, [%4];"
        : "=r"(r[0]), "=r"(r[1]), "=r"(r[2]), "=r"(r[3]) : "r"(a));
}
__device__ __forceinline__ void ldsm_x4_t(u32* r, u32 a) {
    asm volatile("ldmatrix.sync.aligned.m8n8.x4.trans.shared.b16 {%0,%1,%2,%3}, [%4];"
        : "=r"(r[0]), "=r"(r[1]), "=r"(r[2]), "=r"(r[3]) : "r"(a));
}
__device__ __forceinline__ void mma16816(float* c, const u32* a, u32 b0, u32 b1) {
    asm volatile("mma.sync.aligned.m16n8k16.row.col.f32.bf16.bf16.f32 "
        "{%0,%1,%2,%3}, {%4,%5,%6,%7}, {%8,%9}, {%0,%1,%2,%3};"
        : "+f"(c[0]), "+f"(c[1]), "+f"(c[2]), "+f"(c[3])
        : "r"(a[0]), "r"(a[1]), "r"(a[2]), "r"(a[3]), "r"(b0), "r"(b1));
}
__device__ __forceinline__ void mma16832f8(float* c, const u32* a, u32 b0, u32 b1) {
    asm volatile("mma.sync.aligned.m16n8k32.row.col.f32.e4m3.e4m3.f32 "
        "{%0,%1,%2,%3}, {%4,%5,%6,%7}, {%8,%9}, {%0,%1,%2,%3};"
        : "+f"(c[0]), "+f"(c[1]), "+f"(c[2]), "+f"(c[3])
        : "r"(a[0]), "r"(a[1]), "r"(a[2]), "r"(a[3]), "r"(b0), "r"(b1));
}
__device__ __forceinline__ u32 f2bf2(float lo, float hi) {
    __nv_bfloat162 h2 = __floats2bfloat162_rn(lo, hi);
    return *reinterpret_cast<u32*>(&h2);
}
__device__ __forceinline__ u32 hadd_relu2(u32 ua, u32 ub) {
    __nv_bfloat162 a = *reinterpret_cast<__nv_bfloat162*>(&ua);
    __nv_bfloat162 b = *reinterpret_cast<__nv_bfloat162*>(&ub);
    u32 uz = 0u;
    __nv_bfloat162 z = *reinterpret_cast<__nv_bfloat162*>(&uz);
    __nv_bfloat162 r = __hmax2(__hadd2(a, b), z);
    return *reinterpret_cast<u32*>(&r);
}
__device__ __forceinline__ u32 hmax2u(u32 ua, u32 ub) {
    __nv_bfloat162 a = *reinterpret_cast<__nv_bfloat162*>(&ua);
    __nv_bfloat162 b = *reinterpret_cast<__nv_bfloat162*>(&ub);
    __nv_bfloat162 r = __hmax2(a, b);
    return *reinterpret_cast<u32*>(&r);
}
// two f32 -> packed e4m3x2 (hi into upper byte, lo into lower byte)
__device__ __forceinline__ u16 f2e4m3x2(float hi, float lo) {
    u16 q;
    asm("cvt.rn.satfinite.e4m3x2.f32 %0, %1, %2;" : "=h"(q) : "f"(hi), "f"(lo));
    return q;
}
// two bf16x2 pairs (elems 0,1 and 2,3) -> 4 e4m3 bytes in a u32
__device__ __forceinline__ u32 bfp_to_e4m3x4(u32 p01, u32 p23) {
    float2 f0 = __bfloat1622float2(*reinterpret_cast<__nv_bfloat162*>(&p01));
    float2 f1 = __bfloat1622float2(*reinterpret_cast<__nv_bfloat162*>(&p23));
    u16 q0 = f2e4m3x2(f0.y, f0.x);
    u16 q1 = f2e4m3x2(f1.y, f1.x);
    return (u32)q0 | ((u32)q1 << 16);
}

// ---------------------------------------------------------------------------
// K0 (launch 0): merged init.
//  - per-node layer-1 terms (bf16, 4 channels/thread) + zero AGG
//  - w2 -> transposed e4m3 [c][k] rows; w3/w4 -> bf16
//  - dst-degree histogram (g_cnt is zero on entry: static init / scan restore)
// ---------------------------------------------------------------------------
__global__ void k_init(const float* __restrict__ x,
                       const float* __restrict__ w1,
                       const float* __restrict__ b1,
                       const float* __restrict__ w2,
                       const float* __restrict__ w3,
                       const float* __restrict__ w4,
                       const int* __restrict__ ei, int n, int E)
{
    int idx = blockIdx.x * 256 + threadIdx.x;

    if (idx < n * 32) {
        int i  = idx >> 5;          // node
        int q  = idx & 31;
        int c4 = q * 4;             // channel quad
        float x0 = x[i*3+0], x1 = x[i*3+1], x2 = x[i*3+2];
        float4 w0  = *(const float4*)(w1 + 0*HID + c4);
        float4 w1r = *(const float4*)(w1 + 1*HID + c4);
        float4 w2r = *(const float4*)(w1 + 2*HID + c4);
        float4 w3r = *(const float4*)(w1 + 3*HID + c4);
        float4 w4r = *(const float4*)(w1 + 4*HID + c4);
        float4 w5r = *(const float4*)(w1 + 5*HID + c4);
        float4 bb  = *(const float4*)(b1 + c4);

        float B0 = x0*w3r.x + x1*w4r.x + x2*w5r.x;
        float B1 = x0*w3r.y + x1*w4r.y + x2*w5r.y;
        float B2 = x0*w3r.z + x1*w4r.z + x2*w5r.z;
        float B3 = x0*w3r.w + x1*w4r.w + x2*w5r.w;
        float A0 = x0*(w0.x - w3r.x) + x1*(w1r.x - w4r.x) + x2*(w2r.x - w5r.x) + bb.x;
        float A1 = x0*(w0.y - w3r.y) + x1*(w1r.y - w4r.y) + x2*(w2r.y - w5r.y) + bb.y;
        float A2 = x0*(w0.z - w3r.z) + x1*(w1r.z - w4r.z) + x2*(w2r.z - w5r.z) + bb.z;
        float A3 = x0*(w0.w - w3r.w) + x1*(w1r.w - w4r.w) + x2*(w2r.w - w5r.w) + bb.w;

        size_t base = (size_t)i * HID + c4;
        uint2 av, bv;
        av.x = f2bf2(A0, A1); av.y = f2bf2(A2, A3);
        bv.x = f2bf2(B0, B1); bv.y = f2bf2(B2, B3);
        *(uint2*)(g_Abf + base) = av;
        *(uint2*)(g_Bbf + base) = bv;
        *(uint4*)(g_AGG + base) = make_uint4(0u, 0u, 0u, 0u);
    }

    const int P = HID * HID / 2;              // 8192
    if (idx < 4096) {
        // w2^T fp8: u32 at [c][kq], holds w2[4kq..4kq+3][c]
        int c  = idx >> 5;
        int kq = idx & 31;
        float v0 = w2[(4*kq+0)*HID + c];
        float v1 = w2[(4*kq+1)*HID + c];
        float v2 = w2[(4*kq+2)*HID + c];
        float v3 = w2[(4*kq+3)*HID + c];
        u16 q0 = f2e4m3x2(v1, v0);
        u16 q1 = f2e4m3x2(v3, v2);
        g_w2f8[c * (SROW/4) + kq] = (u32)q0 | ((u32)q1 << 16);
    } else if (idx < 4096 + P) {
        float2 v = ((const float2*)w3)[idx - 4096];
        ((u32*)g_w3bf)[idx - 4096] = f2bf2(v.x, v.y);
    } else if (idx < 4096 + 2*P) {
        float2 v = ((const float2*)w4)[idx - 4096 - P];
        ((u32*)g_w4bf)[idx - 4096 - P] = f2bf2(v.x, v.y);
    }

    if (idx < E) atomicAdd(&g_cnt[ei[E + idx]], 1);
}

// ---------------------------------------------------------------------------
// K1 (launch 1): fused scan; restores g_cnt/g_done for replay.
// ---------------------------------------------------------------------------
__global__ void __launch_bounds__(1024, 1) k_scan12(int n, int nb)
{
    __shared__ int wsum[32];
    __shared__ int slast;
    int tid  = threadIdx.x;
    int lane = tid & 31;
    int w    = tid >> 5;
    int i = blockIdx.x * 1024 + tid;
    int v = (i < n) ? g_cnt[i] : 0;
    if (i < n) g_cnt[i] = 0;                   // restore for next replay
    int xv = v;
    #pragma unroll
    for (int off = 1; off < 32; off <<= 1) {
        int y = __shfl_up_sync(0xffffffffu, xv, off);
        if (lane >= off) xv += y;
    }
    if (lane == 31) wsum[w] = xv;
    __syncthreads();
    if (w == 0) {
        int t = wsum[lane];
        #pragma unroll
        for (int off = 1; off < 32; off <<= 1) {
            int y = __shfl_up_sync(0xffffffffu, t, off);
            if (lane >= off) t += y;
        }
        wsum[lane] = t;
    }
    __syncthreads();
    int woff = (w > 0) ? wsum[w - 1] : 0;
    if (i < n) g_off[i] = woff + xv - v;       // block-local exclusive
    if (tid == 0) g_bsum[blockIdx.x] = wsum[31];

    __threadfence();
    if (tid == 0) slast = (atomicAdd(&g_done, 1) == nb - 1) ? 1 : 0;
    __syncthreads();
    if (slast) {
        __threadfence();
        if (tid < 32) {
            int carry = 0;
            for (int base = 0; base < nb; base += 32) {
                int j = base + tid;
                int bv = (j < nb) ? g_bsum[j] : 0;
                int sx = bv;
                #pragma unroll
                for (int off = 1; off < 32; off <<= 1) {
                    int y = __shfl_up_sync(0xffffffffu, sx, off);
                    if (tid >= off) sx += y;
                }
                if (j < nb) g_bsum[j] = carry + sx - bv;
                carry += __shfl_sync(0xffffffffu, sx, 31);
            }
        }
        if (tid == 0) g_done = 0;
    }
}

// ---------------------------------------------------------------------------
// K2 (launch 2): scatter edges into dst-sorted order.
// ---------------------------------------------------------------------------
__global__ void k_scatter(const int* __restrict__ ei, int E)
{
    int e = blockIdx.x * 256 + threadIdx.x;
    if (e < E) {
        int s = ei[e];
        int d = ei[E + e];
        int p = atomicAdd(&g_off[d], 1) + g_bsum[d >> 10];
        g_sedge[p] = make_int2(s, d);
    }
}

// ---------------------------------------------------------------------------
// K3 (launch 3 — ncu profile slot): persistent fp8 mma.sync edge kernel.
// smem: sw2f8 [128 ch][144B] e4m3 (once) | sa8 [128 e][144B] e4m3
//       h-tile overlays sa8 as bf16x2 [128 e][68 u32].
// ---------------------------------------------------------------------------
__global__ void __launch_bounds__(256, 2)
k_edge(int E, const float* __restrict__ b2)
{
    extern __shared__ char smraw[];
    char* sw2f8 = smraw;                    // 18432 B
    char* sa8   = smraw + 18432;            // 18432 B (h overlay 34816 B)
    u32*  shu   = (u32*)sa8;
    __shared__ int sdst[TE];

    int tid  = threadIdx.x;
    int lane = tid & 31;
    int wid  = tid >> 5;

    // load w2^T fp8 once (1152 uint4)
    {
        const uint4* gv = (const uint4*)g_w2f8;
        uint4* sv = (uint4*)sw2f8;
        #pragma unroll
        for (int it = 0; it < 5; it++) {
            int idx = tid + it * 256;
            if (idx < 1152) sv[idx] = gv[idx];
        }
    }
    __syncthreads();

    int e0     = (wid >> 1) * 32;
    int n0w    = (wid & 1) * 64;
    int rsel   = lane & 15;
    int csel16 = (lane >> 4) << 4;    // byte offset for k-half
    int r0     = lane >> 2;
    int cq     = (lane & 3) * 2;

    int ntiles = (E + TE - 1) / TE;

    for (int tile = blockIdx.x; tile < ntiles; tile += gridDim.x) {
        int tile0 = tile * TE;

        // gather relu(A[dst]+B[src]) bf16 -> e4m3, 2 threads/edge
        {
            int e  = tid >> 1;
            int hf = tid & 1;
            int eg = tile0 + e;
            if (eg < E) {
                int2 sd = g_sedge[eg];
                if (hf == 0) sdst[e] = sd.y;
                const uint4* Av = (const uint4*)(g_Abf + (size_t)sd.y * HID) + hf*8;
                const uint4* Bv = (const uint4*)(g_Bbf + (size_t)sd.x * HID) + hf*8;
                #pragma unroll
                for (int j = 0; j < 4; j++) {
                    uint4 a0 = Av[2*j], a1 = Av[2*j+1];
                    uint4 b0 = Bv[2*j], b1 = Bv[2*j+1];
                    uint4 r;
                    r.x = bfp_to_e4m3x4(hadd_relu2(a0.x, b0.x), hadd_relu2(a0.y, b0.y));
                    r.y = bfp_to_e4m3x4(hadd_relu2(a0.z, b0.z), hadd_relu2(a0.w, b0.w));
                    r.z = bfp_to_e4m3x4(hadd_relu2(a1.x, b1.x), hadd_relu2(a1.y, b1.y));
                    r.w = bfp_to_e4m3x4(hadd_relu2(a1.z, b1.z), hadd_relu2(a1.w, b1.w));
                    *(uint4*)(sa8 + e * SROW + hf*64 + j*16) = r;
                }
            } else {
                if (hf == 0) sdst[e] = -1;
                uint4 z = make_uint4(0u, 0u, 0u, 0u);
                #pragma unroll
                for (int j = 0; j < 4; j++)
                    *(uint4*)(sa8 + e * SROW + hf*64 + j*16) = z;
            }
        }
        __syncthreads();

        float acc[2][8][4];
        #pragma unroll
        for (int m = 0; m < 2; m++) {
            #pragma unroll
            for (int t = 0; t < 8; t++) {
                #pragma unroll
                for (int i = 0; i < 4; i++) acc[m][t][i] = 0.f;
            }
        }

        #pragma unroll
        for (int ks = 0; ks < 4; ks++) {
            int kb = ks * 32;           // byte offset along k
            u32 A0[4];
            u32 A1[4];
            ldsm_x4(A0, smaddr(sa8 + (e0 +      rsel) * SROW + kb + csel16));
            ldsm_x4(A1, smaddr(sa8 + (e0 + 16 + rsel) * SROW + kb + csel16));
            #pragma unroll
            for (int t = 0; t < 4; t++) {
                u32 Bf[4];
                ldsm_x4(Bf, smaddr(sw2f8 + (n0w + t*16 + rsel) * SROW + kb + csel16));
                // n8 tile 0 (ch 0-7 of chunk): k-halves (r0, r2); tile 1: (r1, r3)
                mma16832f8(acc[0][2*t+0], A0, Bf[0], Bf[2]);
                mma16832f8(acc[0][2*t+1], A0, Bf[1], Bf[3]);
                mma16832f8(acc[1][2*t+0], A1, Bf[0], Bf[2]);
                mma16832f8(acc[1][2*t+1], A1, Bf[1], Bf[3]);
            }
        }
        __syncthreads();   // all warps done reading sa8 before overlay

        // store h fragments as bf16x2 into shu [edge][64 pairs]
        #pragma unroll
        for (int m = 0; m < 2; m++) {
            int rbase = e0 + m*16 + r0;
            #pragma unroll
            for (int t = 0; t < 8; t++) {
                int cp = (n0w + t*8 + cq) >> 1;
                shu[rbase       * (LDW/2) + cp] = f2bf2(acc[m][t][0], acc[m][t][1]);
                shu[(rbase + 8) * (LDW/2) + cp] = f2bf2(acc[m][t][2], acc[m][t][3]);
            }
        }
        __syncthreads();

        // segmented max over dst-groups (packed bf16x2 channel pairs)
        {
            int p  = tid & 63;
            int eb = (tid >> 6) * 32;
            float2 bb = *(const float2*)(b2 + 2*p);
            int prev = sdst[eb];
            u32 mx = shu[eb * (LDW/2) + p];
            #pragma unroll 4
            for (int j = 1; j < 32; j++) {
                int d2 = sdst[eb + j];
                u32 v  = shu[(eb + j) * (LDW/2) + p];
                if (d2 != prev) {
                    if (prev >= 0) {
                        float2 f = __bfloat1622float2(*reinterpret_cast<__nv_bfloat162*>(&mx));
                        atomicMax(g_AGG + (size_t)prev * HID + 2*p,
                                  __float_as_int(fmaxf(f.x + bb.x, 0.f)));
                        atomicMax(g_AGG + (size_t)prev * HID + 2*p + 1,
                                  __float_as_int(fmaxf(f.y + bb.y, 0.f)));
                    }
                    prev = d2;
                    mx = v;
                } else {
                    mx = hmax2u(mx, v);
                }
            }
            if (prev >= 0) {
                float2 f = __bfloat1622float2(*reinterpret_cast<__nv_bfloat162*>(&mx));
                atomicMax(g_AGG + (size_t)prev * HID + 2*p,
                          __float_as_int(fmaxf(f.x + bb.x, 0.f)));
                atomicMax(g_AGG + (size_t)prev * HID + 2*p + 1,
                          __float_as_int(fmaxf(f.y + bb.y, 0.f)));
            }
        }
        __syncthreads();   // protect sa8/shu + sdst before next tile
    }
}

// ---------------------------------------------------------------------------
// K4 (launch 4): bf16 mma.sync node tail (proven).
// ---------------------------------------------------------------------------
__global__ void __launch_bounds__(256, 2)
k_node_post(const float* __restrict__ pos,
            const float* __restrict__ b3, const float* __restrict__ b4,
            const float* __restrict__ w5, const float* __restrict__ b5,
            float* __restrict__ out, int n)
{
    extern __shared__ char smraw2[];
    __nv_bfloat16* sw3 = (__nv_bfloat16*)smraw2;
    __nv_bfloat16* sw4 = sw3 + 128 * LDW;
    __nv_bfloat16* sa  = sw4 + 128 * LDW;
    u32*           sau = (u32*)sa;
    __shared__ float sw5[HID * 3];

    int tid = threadIdx.x;
    int n0 = blockIdx.x * 128;

    {
        const uint4* g3 = (const uint4*)g_w3bf;
        const uint4* g4 = (const uint4*)g_w4bf;
        #pragma unroll
        for (int it = 0; it < 8; it++) {
            int idx = tid + it * 256;
            int k    = idx >> 4;
            int col8 = (idx & 15) * 8;
            *(uint4*)(sw3 + k * LDW + col8) = g3[idx];
            *(uint4*)(sw4 + k * LDW + col8) = g4[idx];
        }
        if (tid < 192) ((float2*)sw5)[tid] = ((const float2*)w5)[tid];
    }

    {
        int r  = tid >> 1;
        int hf = tid & 1;
        int node = n0 + r;
        if (node < n) {
            const float4* Gv = (const float4*)((const float*)g_AGG + (size_t)node * HID) + hf*16;
            #pragma unroll
            for (int j = 0; j < 8; j++) {
                float4 a = Gv[2*j];
                float4 b = Gv[2*j + 1];
                uint4 rr;
                rr.x = f2bf2(a.x, a.y);
                rr.y = f2bf2(a.z, a.w);
                rr.z = f2bf2(b.x, b.y);
                rr.w = f2bf2(b.z, b.w);
                *(uint4*)(sa + r * LDW + hf*64 + j*8) = rr;
            }
        } else {
            uint4 z = make_uint4(0u, 0u, 0u, 0u);
            #pragma unroll
            for (int j = 0; j < 8; j++)
                *(uint4*)(sa + r * LDW + hf*64 + j*8) = z;
        }
    }
    __syncthreads();

    int lane = tid & 31;
    int wid  = tid >> 5;
    int e0   = (wid >> 1) * 32;
    int n0w  = (wid & 1) * 64;
    int rsel = lane & 15;
    int csel = (lane >> 4) << 3;
    int r0   = lane >> 2;
    int cq   = (lane & 3) * 2;

    float acc[2][8][4];

    #pragma unroll
    for (int m = 0; m < 2; m++) {
        #pragma unroll
        for (int t = 0; t < 8; t++) {
            #pragma unroll
            for (int i = 0; i < 4; i++) acc[m][t][i] = 0.f;
        }
    }
    #pragma unroll
    for (int k0 = 0; k0 < HID; k0 += 16) {
        u32 A0[4];
        u32 A1[4];
        ldsm_x4(A0, smaddr(sa + (e0 +      rsel) * LDW + k0 + csel));
        ldsm_x4(A1, smaddr(sa + (e0 + 16 + rsel) * LDW + k0 + csel));
        #pragma unroll
        for (int t = 0; t < 4; t++) {
            u32 Bf[4];
            ldsm_x4_t(Bf, smaddr(sw3 + (k0 + rsel) * LDW + n0w + t*16 + csel));
            mma16816(acc[0][2*t+0], A0, Bf[0], Bf[1]);
            mma16816(acc[0][2*t+1], A0, Bf[2], Bf[3]);
            mma16816(acc[1][2*t+0], A1, Bf[0], Bf[1]);
            mma16816(acc[1][2*t+1], A1, Bf[2], Bf[3]);
        }
    }
    __syncthreads();

    #pragma unroll
    for (int m = 0; m < 2; m++) {
        int rbase = e0 + m*16 + r0;
        #pragma unroll
        for (int t = 0; t < 8; t++) {
            int c = n0w + t*8 + cq;
            float bb0 = b3[c];
            float bb1 = b3[c+1];
            sau[rbase       * (LDW/2) + (c >> 1)] = f2bf2(acc[m][t][0] + bb0, acc[m][t][1] + bb1);
            sau[(rbase + 8) * (LDW/2) + (c >> 1)] = f2bf2(acc[m][t][2] + bb0, acc[m][t][3] + bb1);
        }
    }
    __syncthreads();

    #pragma unroll
    for (int m = 0; m < 2; m++) {
        #pragma unroll
        for (int t = 0; t < 8; t++) {
            #pragma unroll
            for (int i = 0; i < 4; i++) acc[m][t][i] = 0.f;
        }
    }
    #pragma unroll
    for (int k0 = 0; k0 < HID; k0 += 16) {
        u32 A0[4];
        u32 A1[4];
        ldsm_x4(A0, smaddr(sa + (e0 +      rsel) * LDW + k0 + csel));
        ldsm_x4(A1, smaddr(sa + (e0 + 16 + rsel) * LDW + k0 + csel));
        #pragma unroll
        for (int t = 0; t < 4; t++) {
            u32 Bf[4];
            ldsm_x4_t(Bf, smaddr(sw4 + (k0 + rsel) * LDW + n0w + t*16 + csel));
            mma16816(acc[0][2*t+0], A0, Bf[0], Bf[1]);
            mma16816(acc[0][2*t+1], A0, Bf[2], Bf[3]);
            mma16816(acc[1][2*t+0], A1, Bf[0], Bf[1]);
            mma16816(acc[1][2*t+1], A1, Bf[2], Bf[3]);
        }
    }
    __syncthreads();

    #pragma unroll
    for (int m = 0; m < 2; m++) {
        int rbase = e0 + m*16 + r0;
        #pragma unroll
        for (int t = 0; t < 8; t++) {
            int c = n0w + t*8 + cq;
            float bb0 = b4[c];
            float bb1 = b4[c+1];
            sau[rbase       * (LDW/2) + (c >> 1)] =
                f2bf2(fmaxf(acc[m][t][0] + bb0, 0.f), fmaxf(acc[m][t][1] + bb1, 0.f));
            sau[(rbase + 8) * (LDW/2) + (c >> 1)] =
                f2bf2(fmaxf(acc[m][t][2] + bb0, 0.f), fmaxf(acc[m][t][3] + bb1, 0.f));
        }
    }
    __syncthreads();

    {
        int r  = tid >> 1;
        int hf = tid & 1;
        float pd0 = 0.f, pd1 = 0.f, pd2 = 0.f;
        const u32* rowp = sau + r * (LDW/2) + hf*32;
        #pragma unroll 8
        for (int j = 0; j < 32; j++) {
            u32 uv = rowp[j];
            float2 f = __bfloat1622float2(*reinterpret_cast<__nv_bfloat162*>(&uv));
            int c = hf*64 + 2*j;
            pd0 = fmaf(f.x, sw5[c*3+0], pd0);
            pd1 = fmaf(f.x, sw5[c*3+1], pd1);
            pd2 = fmaf(f.x, sw5[c*3+2], pd2);
            pd0 = fmaf(f.y, sw5[c*3+3], pd0);
            pd1 = fmaf(f.y, sw5[c*3+4], pd1);
            pd2 = fmaf(f.y, sw5[c*3+5], pd2);
        }
        pd0 += __shfl_xor_sync(0xffffffffu, pd0, 1);
        pd1 += __shfl_xor_sync(0xffffffffu, pd1, 1);
        pd2 += __shfl_xor_sync(0xffffffffu, pd2, 1);
        int node = n0 + r;
        if (hf == 0 && node < n) {
            out[node*3 + 0] = pos[node*3 + 0] + 0.1f * tanhf(pd0 + b5[0]);
            out[node*3 + 1] = pos[node*3 + 1] + 0.1f * tanhf(pd1 + b5[1]);
            out[node*3 + 2] = pos[node*3 + 2] + 0.1f * tanhf(pd2 + b5[2]);
        }
    }
}

// ---------------------------------------------------------------------------
extern "C" void kernel_launch(void* const* d_in, const int* in_sizes, int n_in,
                              void* d_out, int out_size)
{
    const float* x   = (const float*)d_in[0];
    const float* pos = (const float*)d_in[1];
    const int*   ei  = (const int*)d_in[2];   // int32
    const float* w1 = (const float*)d_in[3];
    const float* b1 = (const float*)d_in[4];
    const float* w2 = (const float*)d_in[5];
    const float* b2 = (const float*)d_in[6];
    const float* w3 = (const float*)d_in[7];
    const float* b3 = (const float*)d_in[8];
    const float* w4 = (const float*)d_in[9];
    const float* b4 = (const float*)d_in[10];
    const float* w5 = (const float*)d_in[11];
    const float* b5 = (const float*)d_in[12];
    float* out = (float*)d_out;

    int n = in_sizes[0] / 3;      // 100000
    int E = in_sizes[2] / 2;      // 1600000

    (void)n_in;
    (void)out_size;

    const int EDGE_SMEM = 18432 + 34816;       // 53248
    const int NODE_SMEM = 3 * 128 * LDW * 2;   // 104448
    cudaFuncSetAttribute(k_edge, cudaFuncAttributeMaxDynamicSharedMemorySize, EDGE_SMEM);
    cudaFuncSetAttribute(k_node_post, cudaFuncAttributeMaxDynamicSharedMemorySize, NODE_SMEM);

    // launch 0: merged init (pre + wconv + hist)
    int ginit = (n * 32 + 255) / 256;
    k_init<<<ginit, 256>>>(x, w1, b1, w2, w3, w4, ei, n, E);

    // launch 1: fused scan
    int nb = (n + 1023) / 1024;
    k_scan12<<<nb, 1024>>>(n, nb);

    // launch 2: scatter
    k_scatter<<<(E + 255) / 256, 256>>>(ei, E);

    // launch 3: persistent fp8 edge kernel (ncu profile slot)
    k_edge<<<296, 256, EDGE_SMEM>>>(E, b2);

    // launch 4: node tail
    int gnode = (n + 127) / 128;
    k_node_post<<<gnode, 256, NODE_SMEM>>>(pos, b3, b4, w5, b5, out, n);
}

// round 17
// speedup vs baseline: 1.0546x; 1.0546x over previous
#include <cuda_runtime.h>
#include <cuda_bf16.h>
#include <cstdint>
#include <math.h>

#define HID   128
#define NMAX  100000
#define EMAX  1600000
#define TE    128    // edges per tile in edge kernel
#define LDW   136    // bf16 row stride in node_post smem
#define SROW  144    // fp8 row stride in edge-kernel smem (36-bank offset)

typedef unsigned long long ull;
typedef unsigned int u32;
typedef unsigned short u16;

// Scratch (static device globals — no runtime allocation).
// g_cnt / g_done rely on static zero-init; both are restored to 0 by k_scan12
// each run, so every graph replay sees the same initial state (deterministic).
__device__ __nv_bfloat16 g_Abf[(size_t)NMAX * HID];  // per-node dst term (bf16)
__device__ __nv_bfloat16 g_Bbf[(size_t)NMAX * HID];  // per-node src term (bf16)
__device__ u32 g_w2f8[HID * (SROW/4)];               // w2^T e4m3 [c][144B rows]
__device__ __nv_bfloat16 g_w3bf[HID * HID];          // [k][c] linear bf16
__device__ __nv_bfloat16 g_w4bf[HID * HID];
__device__ int   g_AGG[(size_t)NMAX * HID]; // relu(segment_max) as float bits
__device__ int   g_cnt[NMAX];               // per-dst degree (zero at kernel entry)
__device__ int   g_off[NMAX];               // block-local exclusive offsets (cursors)
__device__ int   g_bsum[128];               // per-scan-block totals (scanned)
__device__ int   g_done;                    // scan completion counter (self-reset)
__device__ int2  g_sedge[EMAX];             // (src, dst) sorted by dst

// ---- helpers ---------------------------------------------------------------
__device__ __forceinline__ u32 smaddr(const void* p) {
    return (u32)__cvta_generic_to_shared(p);
}
__device__ __forceinline__ void ldsm_x4(u32* r, u32 a) {
    asm volatile("ldmatrix.sync.aligned.m8n8.x4.shared.b16 {%0,%1,%2,%3}, [%4];"
        : "=r"(r[0]), "=r"(r[1]), "=r"(r[2]), "=r"(r[3]) : "r"(a));
}
__device__ __forceinline__ void ldsm_x4_t(u32* r, u32 a) {
    asm volatile("ldmatrix.sync.aligned.m8n8.x4.trans.shared.b16 {%0,%1,%2,%3}, [%4];"
        : "=r"(r[0]), "=r"(r[1]), "=r"(r[2]), "=r"(r[3]) : "r"(a));
}
__device__ __forceinline__ void mma16816(float* c, const u32* a, u32 b0, u32 b1) {
    asm volatile("mma.sync.aligned.m16n8k16.row.col.f32.bf16.bf16.f32 "
        "{%0,%1,%2,%3}, {%4,%5,%6,%7}, {%8,%9}, {%0,%1,%2,%3};"
        : "+f"(c[0]), "+f"(c[1]), "+f"(c[2]), "+f"(c[3])
        : "r"(a[0]), "r"(a[1]), "r"(a[2]), "r"(a[3]), "r"(b0), "r"(b1));
}
__device__ __forceinline__ void mma16832f8(float* c, const u32* a, u32 b0, u32 b1) {
    asm volatile("mma.sync.aligned.m16n8k32.row.col.f32.e4m3.e4m3.f32 "
        "{%0,%1,%2,%3}, {%4,%5,%6,%7}, {%8,%9}, {%0,%1,%2,%3};"
        : "+f"(c[0]), "+f"(c[1]), "+f"(c[2]), "+f"(c[3])
        : "r"(a[0]), "r"(a[1]), "r"(a[2]), "r"(a[3]), "r"(b0), "r"(b1));
}
__device__ __forceinline__ u32 f2bf2(float lo, float hi) {
    __nv_bfloat162 h2 = __floats2bfloat162_rn(lo, hi);
    return *reinterpret_cast<u32*>(&h2);
}
__device__ __forceinline__ u32 hadd_relu2(u32 ua, u32 ub) {
    __nv_bfloat162 a = *reinterpret_cast<__nv_bfloat162*>(&ua);
    __nv_bfloat162 b = *reinterpret_cast<__nv_bfloat162*>(&ub);
    u32 uz = 0u;
    __nv_bfloat162 z = *reinterpret_cast<__nv_bfloat162*>(&uz);
    __nv_bfloat162 r = __hmax2(__hadd2(a, b), z);
    return *reinterpret_cast<u32*>(&r);
}
__device__ __forceinline__ u32 hmax2u(u32 ua, u32 ub) {
    __nv_bfloat162 a = *reinterpret_cast<__nv_bfloat162*>(&ua);
    __nv_bfloat162 b = *reinterpret_cast<__nv_bfloat162*>(&ub);
    __nv_bfloat162 r = __hmax2(a, b);
    return *reinterpret_cast<u32*>(&r);
}
// two f32 -> packed e4m3x2 (hi into upper byte, lo into lower byte)
__device__ __forceinline__ u16 f2e4m3x2(float hi, float lo) {
    u16 q;
    asm("cvt.rn.satfinite.e4m3x2.f32 %0, %1, %2;" : "=h"(q) : "f"(hi), "f"(lo));
    return q;
}
// two bf16x2 pairs (elems 0,1 and 2,3) -> 4 e4m3 bytes in a u32
__device__ __forceinline__ u32 bfp_to_e4m3x4(u32 p01, u32 p23) {
    float2 f0 = __bfloat1622float2(*reinterpret_cast<__nv_bfloat162*>(&p01));
    float2 f1 = __bfloat1622float2(*reinterpret_cast<__nv_bfloat162*>(&p23));
    u16 q0 = f2e4m3x2(f0.y, f0.x);
    u16 q1 = f2e4m3x2(f1.y, f1.x);
    return (u32)q0 | ((u32)q1 << 16);
}

// ---------------------------------------------------------------------------
// K0 (launch 0): merged init.
// ---------------------------------------------------------------------------
__global__ void k_init(const float* __restrict__ x,
                       const float* __restrict__ w1,
                       const float* __restrict__ b1,
                       const float* __restrict__ w2,
                       const float* __restrict__ w3,
                       const float* __restrict__ w4,
                       const int* __restrict__ ei, int n, int E)
{
    int idx = blockIdx.x * 256 + threadIdx.x;

    if (idx < n * 32) {
        int i  = idx >> 5;          // node
        int q  = idx & 31;
        int c4 = q * 4;             // channel quad
        float x0 = x[i*3+0], x1 = x[i*3+1], x2 = x[i*3+2];
        float4 w0  = *(const float4*)(w1 + 0*HID + c4);
        float4 w1r = *(const float4*)(w1 + 1*HID + c4);
        float4 w2r = *(const float4*)(w1 + 2*HID + c4);
        float4 w3r = *(const float4*)(w1 + 3*HID + c4);
        float4 w4r = *(const float4*)(w1 + 4*HID + c4);
        float4 w5r = *(const float4*)(w1 + 5*HID + c4);
        float4 bb  = *(const float4*)(b1 + c4);

        float B0 = x0*w3r.x + x1*w4r.x + x2*w5r.x;
        float B1 = x0*w3r.y + x1*w4r.y + x2*w5r.y;
        float B2 = x0*w3r.z + x1*w4r.z + x2*w5r.z;
        float B3 = x0*w3r.w + x1*w4r.w + x2*w5r.w;
        float A0 = x0*(w0.x - w3r.x) + x1*(w1r.x - w4r.x) + x2*(w2r.x - w5r.x) + bb.x;
        float A1 = x0*(w0.y - w3r.y) + x1*(w1r.y - w4r.y) + x2*(w2r.y - w5r.y) + bb.y;
        float A2 = x0*(w0.z - w3r.z) + x1*(w1r.z - w4r.z) + x2*(w2r.z - w5r.z) + bb.z;
        float A3 = x0*(w0.w - w3r.w) + x1*(w1r.w - w4r.w) + x2*(w2r.w - w5r.w) + bb.w;

        size_t base = (size_t)i * HID + c4;
        uint2 av, bv;
        av.x = f2bf2(A0, A1); av.y = f2bf2(A2, A3);
        bv.x = f2bf2(B0, B1); bv.y = f2bf2(B2, B3);
        *(uint2*)(g_Abf + base) = av;
        *(uint2*)(g_Bbf + base) = bv;
        *(uint4*)(g_AGG + base) = make_uint4(0u, 0u, 0u, 0u);
    }

    const int P = HID * HID / 2;              // 8192
    if (idx < 4096) {
        // w2^T fp8: u32 at [c][kq], holds w2[4kq..4kq+3][c]
        int c  = idx >> 5;
        int kq = idx & 31;
        float v0 = w2[(4*kq+0)*HID + c];
        float v1 = w2[(4*kq+1)*HID + c];
        float v2 = w2[(4*kq+2)*HID + c];
        float v3 = w2[(4*kq+3)*HID + c];
        u16 q0 = f2e4m3x2(v1, v0);
        u16 q1 = f2e4m3x2(v3, v2);
        g_w2f8[c * (SROW/4) + kq] = (u32)q0 | ((u32)q1 << 16);
    } else if (idx < 4096 + P) {
        float2 v = ((const float2*)w3)[idx - 4096];
        ((u32*)g_w3bf)[idx - 4096] = f2bf2(v.x, v.y);
    } else if (idx < 4096 + 2*P) {
        float2 v = ((const float2*)w4)[idx - 4096 - P];
        ((u32*)g_w4bf)[idx - 4096 - P] = f2bf2(v.x, v.y);
    }

    if (idx < E) atomicAdd(&g_cnt[ei[E + idx]], 1);
}

// ---------------------------------------------------------------------------
// K1 (launch 1): fused scan; restores g_cnt/g_done for replay.
// ---------------------------------------------------------------------------
__global__ void __launch_bounds__(1024, 1) k_scan12(int n, int nb)
{
    __shared__ int wsum[32];
    __shared__ int slast;
    int tid  = threadIdx.x;
    int lane = tid & 31;
    int w    = tid >> 5;
    int i = blockIdx.x * 1024 + tid;
    int v = (i < n) ? g_cnt[i] : 0;
    if (i < n) g_cnt[i] = 0;                   // restore for next replay
    int xv = v;
    #pragma unroll
    for (int off = 1; off < 32; off <<= 1) {
        int y = __shfl_up_sync(0xffffffffu, xv, off);
        if (lane >= off) xv += y;
    }
    if (lane == 31) wsum[w] = xv;
    __syncthreads();
    if (w == 0) {
        int t = wsum[lane];
        #pragma unroll
        for (int off = 1; off < 32; off <<= 1) {
            int y = __shfl_up_sync(0xffffffffu, t, off);
            if (lane >= off) t += y;
        }
        wsum[lane] = t;
    }
    __syncthreads();
    int woff = (w > 0) ? wsum[w - 1] : 0;
    if (i < n) g_off[i] = woff + xv - v;       // block-local exclusive
    if (tid == 0) g_bsum[blockIdx.x] = wsum[31];

    __threadfence();
    if (tid == 0) slast = (atomicAdd(&g_done, 1) == nb - 1) ? 1 : 0;
    __syncthreads();
    if (slast) {
        __threadfence();
        if (tid < 32) {
            int carry = 0;
            for (int base = 0; base < nb; base += 32) {
                int j = base + tid;
                int bv = (j < nb) ? g_bsum[j] : 0;
                int sx = bv;
                #pragma unroll
                for (int off = 1; off < 32; off <<= 1) {
                    int y = __shfl_up_sync(0xffffffffu, sx, off);
                    if (tid >= off) sx += y;
                }
                if (j < nb) g_bsum[j] = carry + sx - bv;
                carry += __shfl_sync(0xffffffffu, sx, 31);
            }
        }
        if (tid == 0) g_done = 0;
    }
}

// ---------------------------------------------------------------------------
// K2 (launch 2): scatter edges into dst-sorted order.
// ---------------------------------------------------------------------------
__global__ void k_scatter(const int* __restrict__ ei, int E)
{
    int e = blockIdx.x * 256 + threadIdx.x;
    if (e < E) {
        int s = ei[e];
        int d = ei[E + e];
        int p = atomicAdd(&g_off[d], 1) + g_bsum[d >> 10];
        g_sedge[p] = make_int2(s, d);
    }
}

// ---------------------------------------------------------------------------
// K3 (launch 3 — ncu profile slot): persistent fp8 edge kernel, 512 threads.
// Warp (eg,cg): eg = wid>>2 -> 32 edges, cg = wid&3 -> 32 channels.
// acc[2][4][4] = 32 regs/thread -> 2 CTAs x 512 thr = occ 50%.
// smem: sw2f8 [128 ch][144B] e4m3 (once) | sa8 [128 e][144B] e4m3
//       h-tile overlays sa8 as bf16x2 [128 e][68 u32].
// ---------------------------------------------------------------------------
__global__ void __launch_bounds__(512, 2)
k_edge(int E, const float* __restrict__ b2)
{
    extern __shared__ char smraw[];
    char* sw2f8 = smraw;                    // 18432 B
    char* sa8   = smraw + 18432;            // 18432 B (h overlay 34816 B)
    u32*  shu   = (u32*)sa8;
    __shared__ int sdst[TE];

    int tid  = threadIdx.x;
    int lane = tid & 31;
    int wid  = tid >> 5;

    // load w2^T fp8 once (1152 uint4)
    {
        const uint4* gv = (const uint4*)g_w2f8;
        uint4* sv = (uint4*)sw2f8;
        #pragma unroll
        for (int it = 0; it < 3; it++) {
            int idx = tid + it * 512;
            if (idx < 1152) sv[idx] = gv[idx];
        }
    }
    __syncthreads();

    int e0     = (wid >> 2) * 32;     // 4 edge groups
    int n0w    = (wid & 3) * 32;      // 4 channel groups
    int rsel   = lane & 15;
    int csel16 = (lane >> 4) << 4;    // byte offset for k-half
    int r0     = lane >> 2;
    int cq     = (lane & 3) * 2;

    int ntiles = (E + TE - 1) / TE;

    for (int tile = blockIdx.x; tile < ntiles; tile += gridDim.x) {
        int tile0 = tile * TE;

        // gather relu(A[dst]+B[src]) bf16 -> e4m3, 4 threads/edge
        {
            int e = tid >> 2;
            int q = tid & 3;          // quarter of the 128-ch row
            int eg = tile0 + e;
            if (eg < E) {
                int2 sd = g_sedge[eg];
                if (q == 0) sdst[e] = sd.y;
                const uint4* Av = (const uint4*)(g_Abf + (size_t)sd.y * HID) + q*4;
                const uint4* Bv = (const uint4*)(g_Bbf + (size_t)sd.x * HID) + q*4;
                #pragma unroll
                for (int j = 0; j < 2; j++) {
                    uint4 a0 = Av[2*j], a1 = Av[2*j+1];
                    uint4 b0 = Bv[2*j], b1 = Bv[2*j+1];
                    uint4 r;
                    r.x = bfp_to_e4m3x4(hadd_relu2(a0.x, b0.x), hadd_relu2(a0.y, b0.y));
                    r.y = bfp_to_e4m3x4(hadd_relu2(a0.z, b0.z), hadd_relu2(a0.w, b0.w));
                    r.z = bfp_to_e4m3x4(hadd_relu2(a1.x, b1.x), hadd_relu2(a1.y, b1.y));
                    r.w = bfp_to_e4m3x4(hadd_relu2(a1.z, b1.z), hadd_relu2(a1.w, b1.w));
                    *(uint4*)(sa8 + e * SROW + q*32 + j*16) = r;
                }
            } else {
                if (q == 0) sdst[e] = -1;
                uint4 z = make_uint4(0u, 0u, 0u, 0u);
                #pragma unroll
                for (int j = 0; j < 2; j++)
                    *(uint4*)(sa8 + e * SROW + q*32 + j*16) = z;
            }
        }
        __syncthreads();

        float acc[2][4][4];
        #pragma unroll
        for (int m = 0; m < 2; m++) {
            #pragma unroll
            for (int t = 0; t < 4; t++) {
                #pragma unroll
                for (int i = 0; i < 4; i++) acc[m][t][i] = 0.f;
            }
        }

        #pragma unroll
        for (int ks = 0; ks < 4; ks++) {
            int kb = ks * 32;           // byte offset along k
            u32 A0[4];
            u32 A1[4];
            ldsm_x4(A0, smaddr(sa8 + (e0 +      rsel) * SROW + kb + csel16));
            ldsm_x4(A1, smaddr(sa8 + (e0 + 16 + rsel) * SROW + kb + csel16));
            #pragma unroll
            for (int t = 0; t < 2; t++) {
                u32 Bf[4];
                ldsm_x4(Bf, smaddr(sw2f8 + (n0w + t*16 + rsel) * SROW + kb + csel16));
                mma16832f8(acc[0][2*t+0], A0, Bf[0], Bf[2]);
                mma16832f8(acc[0][2*t+1], A0, Bf[1], Bf[3]);
                mma16832f8(acc[1][2*t+0], A1, Bf[0], Bf[2]);
                mma16832f8(acc[1][2*t+1], A1, Bf[1], Bf[3]);
            }
        }
        __syncthreads();   // all warps done reading sa8 before overlay

        // store h fragments as bf16x2 into shu [edge][64 pairs]
        #pragma unroll
        for (int m = 0; m < 2; m++) {
            int rbase = e0 + m*16 + r0;
            #pragma unroll
            for (int t = 0; t < 4; t++) {
                int cp = (n0w + t*8 + cq) >> 1;
                shu[rbase       * (LDW/2) + cp] = f2bf2(acc[m][t][0], acc[m][t][1]);
                shu[(rbase + 8) * (LDW/2) + cp] = f2bf2(acc[m][t][2], acc[m][t][3]);
            }
        }
        __syncthreads();

        // segmented max over dst-groups: 512 threads -> 8 groups of 16 edges
        {
            int p  = tid & 63;
            int eb = (tid >> 6) * 16;
            float2 bb = *(const float2*)(b2 + 2*p);
            int prev = sdst[eb];
            u32 mx = shu[eb * (LDW/2) + p];
            #pragma unroll 4
            for (int j = 1; j < 16; j++) {
                int d2 = sdst[eb + j];
                u32 v  = shu[(eb + j) * (LDW/2) + p];
                if (d2 != prev) {
                    if (prev >= 0) {
                        float2 f = __bfloat1622float2(*reinterpret_cast<__nv_bfloat162*>(&mx));
                        atomicMax(g_AGG + (size_t)prev * HID + 2*p,
                                  __float_as_int(fmaxf(f.x + bb.x, 0.f)));
                        atomicMax(g_AGG + (size_t)prev * HID + 2*p + 1,
                                  __float_as_int(fmaxf(f.y + bb.y, 0.f)));
                    }
                    prev = d2;
                    mx = v;
                } else {
                    mx = hmax2u(mx, v);
                }
            }
            if (prev >= 0) {
                float2 f = __bfloat1622float2(*reinterpret_cast<__nv_bfloat162*>(&mx));
                atomicMax(g_AGG + (size_t)prev * HID + 2*p,
                          __float_as_int(fmaxf(f.x + bb.x, 0.f)));
                atomicMax(g_AGG + (size_t)prev * HID + 2*p + 1,
                          __float_as_int(fmaxf(f.y + bb.y, 0.f)));
            }
        }
        __syncthreads();   // protect sa8/shu + sdst before next tile
    }
}

// ---------------------------------------------------------------------------
// K4 (launch 4): bf16 mma.sync node tail (proven).
// ---------------------------------------------------------------------------
__global__ void __launch_bounds__(256, 2)
k_node_post(const float* __restrict__ pos,
            const float* __restrict__ b3, const float* __restrict__ b4,
            const float* __restrict__ w5, const float* __restrict__ b5,
            float* __restrict__ out, int n)
{
    extern __shared__ char smraw2[];
    __nv_bfloat16* sw3 = (__nv_bfloat16*)smraw2;
    __nv_bfloat16* sw4 = sw3 + 128 * LDW;
    __nv_bfloat16* sa  = sw4 + 128 * LDW;
    u32*           sau = (u32*)sa;
    __shared__ float sw5[HID * 3];

    int tid = threadIdx.x;
    int n0 = blockIdx.x * 128;

    {
        const uint4* g3 = (const uint4*)g_w3bf;
        const uint4* g4 = (const uint4*)g_w4bf;
        #pragma unroll
        for (int it = 0; it < 8; it++) {
            int idx = tid + it * 256;
            int k    = idx >> 4;
            int col8 = (idx & 15) * 8;
            *(uint4*)(sw3 + k * LDW + col8) = g3[idx];
            *(uint4*)(sw4 + k * LDW + col8) = g4[idx];
        }
        if (tid < 192) ((float2*)sw5)[tid] = ((const float2*)w5)[tid];
    }

    {
        int r  = tid >> 1;
        int hf = tid & 1;
        int node = n0 + r;
        if (node < n) {
            const float4* Gv = (const float4*)((const float*)g_AGG + (size_t)node * HID) + hf*16;
            #pragma unroll
            for (int j = 0; j < 8; j++) {
                float4 a = Gv[2*j];
                float4 b = Gv[2*j + 1];
                uint4 rr;
                rr.x = f2bf2(a.x, a.y);
                rr.y = f2bf2(a.z, a.w);
                rr.z = f2bf2(b.x, b.y);
                rr.w = f2bf2(b.z, b.w);
                *(uint4*)(sa + r * LDW + hf*64 + j*8) = rr;
            }
        } else {
            uint4 z = make_uint4(0u, 0u, 0u, 0u);
            #pragma unroll
            for (int j = 0; j < 8; j++)
                *(uint4*)(sa + r * LDW + hf*64 + j*8) = z;
        }
    }
    __syncthreads();

    int lane = tid & 31;
    int wid  = tid >> 5;
    int e0   = (wid >> 1) * 32;
    int n0w  = (wid & 1) * 64;
    int rsel = lane & 15;
    int csel = (lane >> 4) << 3;
    int r0   = lane >> 2;
    int cq   = (lane & 3) * 2;

    float acc[2][8][4];

    #pragma unroll
    for (int m = 0; m < 2; m++) {
        #pragma unroll
        for (int t = 0; t < 8; t++) {
            #pragma unroll
            for (int i = 0; i < 4; i++) acc[m][t][i] = 0.f;
        }
    }
    #pragma unroll
    for (int k0 = 0; k0 < HID; k0 += 16) {
        u32 A0[4];
        u32 A1[4];
        ldsm_x4(A0, smaddr(sa + (e0 +      rsel) * LDW + k0 + csel));
        ldsm_x4(A1, smaddr(sa + (e0 + 16 + rsel) * LDW + k0 + csel));
        #pragma unroll
        for (int t = 0; t < 4; t++) {
            u32 Bf[4];
            ldsm_x4_t(Bf, smaddr(sw3 + (k0 + rsel) * LDW + n0w + t*16 + csel));
            mma16816(acc[0][2*t+0], A0, Bf[0], Bf[1]);
            mma16816(acc[0][2*t+1], A0, Bf[2], Bf[3]);
            mma16816(acc[1][2*t+0], A1, Bf[0], Bf[1]);
            mma16816(acc[1][2*t+1], A1, Bf[2], Bf[3]);
        }
    }
    __syncthreads();

    #pragma unroll
    for (int m = 0; m < 2; m++) {
        int rbase = e0 + m*16 + r0;
        #pragma unroll
        for (int t = 0; t < 8; t++) {
            int c = n0w + t*8 + cq;
            float bb0 = b3[c];
            float bb1 = b3[c+1];
            sau[rbase       * (LDW/2) + (c >> 1)] = f2bf2(acc[m][t][0] + bb0, acc[m][t][1] + bb1);
            sau[(rbase + 8) * (LDW/2) + (c >> 1)] = f2bf2(acc[m][t][2] + bb0, acc[m][t][3] + bb1);
        }
    }
    __syncthreads();

    #pragma unroll
    for (int m = 0; m < 2; m++) {
        #pragma unroll
        for (int t = 0; t < 8; t++) {
            #pragma unroll
            for (int i = 0; i < 4; i++) acc[m][t][i] = 0.f;
        }
    }
    #pragma unroll
    for (int k0 = 0; k0 < HID; k0 += 16) {
        u32 A0[4];
        u32 A1[4];
        ldsm_x4(A0, smaddr(sa + (e0 +      rsel) * LDW + k0 + csel));
        ldsm_x4(A1, smaddr(sa + (e0 + 16 + rsel) * LDW + k0 + csel));
        #pragma unroll
        for (int t = 0; t < 4; t++) {
            u32 Bf[4];
            ldsm_x4_t(Bf, smaddr(sw4 + (k0 + rsel) * LDW + n0w + t*16 + csel));
            mma16816(acc[0][2*t+0], A0, Bf[0], Bf[1]);
            mma16816(acc[0][2*t+1], A0, Bf[2], Bf[3]);
            mma16816(acc[1][2*t+0], A1, Bf[0], Bf[1]);
            mma16816(acc[1][2*t+1], A1, Bf[2], Bf[3]);
        }
    }
    __syncthreads();

    #pragma unroll
    for (int m = 0; m < 2; m++) {
        int rbase = e0 + m*16 + r0;
        #pragma unroll
        for (int t = 0; t < 8; t++) {
            int c = n0w + t*8 + cq;
            float bb0 = b4[c];
            float bb1 = b4[c+1];
            sau[rbase       * (LDW/2) + (c >> 1)] =
                f2bf2(fmaxf(acc[m][t][0] + bb0, 0.f), fmaxf(acc[m][t][1] + bb1, 0.f));
            sau[(rbase + 8) * (LDW/2) + (c >> 1)] =
                f2bf2(fmaxf(acc[m][t][2] + bb0, 0.f), fmaxf(acc[m][t][3] + bb1, 0.f));
        }
    }
    __syncthreads();

    {
        int r  = tid >> 1;
        int hf = tid & 1;
        float pd0 = 0.f, pd1 = 0.f, pd2 = 0.f;
        const u32* rowp = sau + r * (LDW/2) + hf*32;
        #pragma unroll 8
        for (int j = 0; j < 32; j++) {
            u32 uv = rowp[j];
            float2 f = __bfloat1622float2(*reinterpret_cast<__nv_bfloat162*>(&uv));
            int c = hf*64 + 2*j;
            pd0 = fmaf(f.x, sw5[c*3+0], pd0);
            pd1 = fmaf(f.x, sw5[c*3+1], pd1);
            pd2 = fmaf(f.x, sw5[c*3+2], pd2);
            pd0 = fmaf(f.y, sw5[c*3+3], pd0);
            pd1 = fmaf(f.y, sw5[c*3+4], pd1);
            pd2 = fmaf(f.y, sw5[c*3+5], pd2);
        }
        pd0 += __shfl_xor_sync(0xffffffffu, pd0, 1);
        pd1 += __shfl_xor_sync(0xffffffffu, pd1, 1);
        pd2 += __shfl_xor_sync(0xffffffffu, pd2, 1);
        int node = n0 + r;
        if (hf == 0 && node < n) {
            out[node*3 + 0] = pos[node*3 + 0] + 0.1f * tanhf(pd0 + b5[0]);
            out[node*3 + 1] = pos[node*3 + 1] + 0.1f * tanhf(pd1 + b5[1]);
            out[node*3 + 2] = pos[node*3 + 2] + 0.1f * tanhf(pd2 + b5[2]);
        }
    }
}

// ---------------------------------------------------------------------------
extern "C" void kernel_launch(void* const* d_in, const int* in_sizes, int n_in,
                              void* d_out, int out_size)
{
    const float* x   = (const float*)d_in[0];
    const float* pos = (const float*)d_in[1];
    const int*   ei  = (const int*)d_in[2];   // int32
    const float* w1 = (const float*)d_in[3];
    const float* b1 = (const float*)d_in[4];
    const float* w2 = (const float*)d_in[5];
    const float* b2 = (const float*)d_in[6];
    const float* w3 = (const float*)d_in[7];
    const float* b3 = (const float*)d_in[8];
    const float* w4 = (const float*)d_in[9];
    const float* b4 = (const float*)d_in[10];
    const float* w5 = (const float*)d_in[11];
    const float* b5 = (const float*)d_in[12];
    float* out = (float*)d_out;

    int n = in_sizes[0] / 3;      // 100000
    int E = in_sizes[2] / 2;      // 1600000

    (void)n_in;
    (void)out_size;

    const int EDGE_SMEM = 18432 + 34816;       // 53248
    const int NODE_SMEM = 3 * 128 * LDW * 2;   // 104448
    cudaFuncSetAttribute(k_edge, cudaFuncAttributeMaxDynamicSharedMemorySize, EDGE_SMEM);
    cudaFuncSetAttribute(k_node_post, cudaFuncAttributeMaxDynamicSharedMemorySize, NODE_SMEM);

    // launch 0: merged init (pre + wconv + hist)
    int ginit = (n * 32 + 255) / 256;
    k_init<<<ginit, 256>>>(x, w1, b1, w2, w3, w4, ei, n, E);

    // launch 1: fused scan
    int nb = (n + 1023) / 1024;
    k_scan12<<<nb, 1024>>>(n, nb);

    // launch 2: scatter
    k_scatter<<<(E + 255) / 256, 256>>>(ei, E);

    // launch 3: persistent fp8 edge kernel, 512 threads (ncu profile slot)
    k_edge<<<296, 512, EDGE_SMEM>>>(E, b2);

    // launch 4: node tail
    int gnode = (n + 127) / 128;
    k_node_post<<<gnode, 256, NODE_SMEM>>>(pos, b3, b4, w5, b5, out, n);
}